// round 6
// baseline (speedup 1.0000x reference)
#include <cuda_runtime.h>
#include <cuda_bf16.h>
#include <cstdint>

// CycleEmbedding via code-count factorization:
//   out[c,:] = sum_k count[c,k] * emb[k,:],  count[c,k] = #{e: cycle_e=c, x[atom_e]=k}
// x: [100000] int32 (0..21), atom_to_cycle: [2, 600000] int32,
// emb_weight: [22,128] f32, out: [100000,128] f32.
//
// g_counts is zero at module load (static zero-init). expand_kernel restores
// every entry it reads back to zero, so the invariant "counts are all zero at
// kernel_launch entry" holds across the correctness call and all graph replays.

#define HIDDEN 128
#define NUM_CODES 22
#define MAX_SEGMENTS 100000

__device__ int g_counts[MAX_SEGMENTS * NUM_CODES];   // 8.8 MB scratch, zero-init

__global__ void __launch_bounds__(256) count_kernel(
    const int* __restrict__ x,
    const int* __restrict__ atom_idx,
    const int* __restrict__ cycle_idx,
    int E4)                                 // number of 4-edge groups
{
    int g = blockIdx.x * blockDim.x + threadIdx.x;
    if (g >= E4) return;

    int4 a = __ldg(reinterpret_cast<const int4*>(atom_idx) + g);
    int4 c = __ldg(reinterpret_cast<const int4*>(cycle_idx) + g);

    int k0 = __ldg(&x[a.x]);
    int k1 = __ldg(&x[a.y]);
    int k2 = __ldg(&x[a.z]);
    int k3 = __ldg(&x[a.w]);

    atomicAdd(&g_counts[c.x * NUM_CODES + k0], 1);
    atomicAdd(&g_counts[c.y * NUM_CODES + k1], 1);
    atomicAdd(&g_counts[c.z * NUM_CODES + k2], 1);
    atomicAdd(&g_counts[c.w * NUM_CODES + k3], 1);
}

__global__ void __launch_bounds__(256) count_tail_kernel(
    const int* __restrict__ x,
    const int* __restrict__ atom_idx,
    const int* __restrict__ cycle_idx,
    int start, int E)
{
    int e = start + blockIdx.x * blockDim.x + threadIdx.x;
    if (e >= E) return;
    int a = __ldg(&atom_idx[e]);
    int c = __ldg(&cycle_idx[e]);
    int code = __ldg(&x[a]);
    atomicAdd(&g_counts[c * NUM_CODES + code], 1);
}

__global__ void __launch_bounds__(256) expand_kernel(
    const float* __restrict__ emb,       // [22, 128]
    float* __restrict__ out,             // [S, 128]
    int S)
{
    __shared__ float s_emb[NUM_CODES * HIDDEN];      // 11 KB
    for (int i = threadIdx.x; i < NUM_CODES * HIDDEN; i += blockDim.x)
        s_emb[i] = emb[i];
    __syncthreads();

    const int lane = threadIdx.x & 31;
    const int warp = threadIdx.x >> 5;               // 0..7
    const int row = blockIdx.x * 8 + warp;
    if (row >= S) return;

    // lanes 0..21 load this row's counts (88B contiguous), then restore zeros
    int cnt = 0;
    if (lane < NUM_CODES) {
        int* p = &g_counts[row * NUM_CODES + lane];
        cnt = *p;
        *p = 0;                                      // reset for next launch
    }

    float4 acc = make_float4(0.f, 0.f, 0.f, 0.f);
    const float4* embv = reinterpret_cast<const float4*>(s_emb);

    #pragma unroll
    for (int k = 0; k < NUM_CODES; k++) {
        int ck = __shfl_sync(0xffffffffu, cnt, k);
        if (ck) {
            float f = (float)ck;
            float4 e = embv[k * 32 + lane];          // LDS.128, conflict-free
            acc.x += f * e.x; acc.y += f * e.y;
            acc.z += f * e.z; acc.w += f * e.w;
        }
    }

    reinterpret_cast<float4*>(out)[(size_t)row * 32 + lane] = acc;
}

extern "C" void kernel_launch(void* const* d_in, const int* in_sizes, int n_in,
                              void* d_out, int out_size)
{
    const int*   x   = (const int*)d_in[0];
    const int*   a2c = (const int*)d_in[1];
    const float* emb = (const float*)d_in[2];
    float*       out = (float*)d_out;

    const int E = in_sizes[1] / 2;                   // 600000
    const int S = out_size / HIDDEN;                 // 100000
    const int* atom_idx  = a2c;
    const int* cycle_idx = a2c + E;

    // 1) histogram edges into (cycle, code) counts, 4 edges/thread.
    //    int4 path requires cycle_idx 16B-aligned: true iff E % 4 == 0.
    if ((E & 3) == 0) {
        int E4 = E >> 2;
        count_kernel<<<(E4 + 255) / 256, 256>>>(x, atom_idx, cycle_idx, E4);
    } else {
        count_tail_kernel<<<(E + 255) / 256, 256>>>(x, atom_idx, cycle_idx, 0, E);
    }

    // 2) expand counts -> output rows (one warp per row); also re-zeros counts
    expand_kernel<<<(S + 7) / 8, 256>>>(emb, out, S);
}

// round 7
// speedup vs baseline: 1.7678x; 1.7678x over previous
#include <cuda_runtime.h>
#include <cuda_bf16.h>
#include <cstdint>

// CycleEmbedding via code-count factorization:
//   out[c,:] = sum_k count[c,k] * emb[k,:],  count[c,k] = #{e: cycle_e=c, x[atom_e]=k}
// x: [100000] int32 (0..21), atom_to_cycle: [2, 600000] int32,
// emb_weight: [22,128] f32, out: [100000,128] f32.
//
// g_counts is zero-initialized at module load. expand_kernel restores every
// entry it reads back to zero (coalesced int4 stores), so the invariant
// "counts all zero at kernel_launch entry" holds across correctness run,
// capture, and every graph replay.

#define HIDDEN 128
#define NUM_CODES 22
#define MAX_SEGMENTS 100000
#define ROWS_PER_BLOCK 32
#define ETHREADS 256

__device__ int g_counts[MAX_SEGMENTS * NUM_CODES];   // 8.8 MB scratch, zero-init

__global__ void __launch_bounds__(256) count_kernel(
    const int* __restrict__ x,
    const int* __restrict__ atom_idx,
    const int* __restrict__ cycle_idx,
    int E4)                                 // number of 4-edge groups
{
    int g = blockIdx.x * blockDim.x + threadIdx.x;
    if (g >= E4) return;

    int4 a = __ldg(reinterpret_cast<const int4*>(atom_idx) + g);
    int4 c = __ldg(reinterpret_cast<const int4*>(cycle_idx) + g);

    int k0 = __ldg(&x[a.x]);
    int k1 = __ldg(&x[a.y]);
    int k2 = __ldg(&x[a.z]);
    int k3 = __ldg(&x[a.w]);

    atomicAdd(&g_counts[c.x * NUM_CODES + k0], 1);
    atomicAdd(&g_counts[c.y * NUM_CODES + k1], 1);
    atomicAdd(&g_counts[c.z * NUM_CODES + k2], 1);
    atomicAdd(&g_counts[c.w * NUM_CODES + k3], 1);
}

__global__ void __launch_bounds__(256) count_tail_kernel(
    const int* __restrict__ x,
    const int* __restrict__ atom_idx,
    const int* __restrict__ cycle_idx,
    int E)
{
    int e = blockIdx.x * blockDim.x + threadIdx.x;
    if (e >= E) return;
    int a = __ldg(&atom_idx[e]);
    int c = __ldg(&cycle_idx[e]);
    int code = __ldg(&x[a]);
    atomicAdd(&g_counts[c * NUM_CODES + code], 1);
}

__global__ void __launch_bounds__(ETHREADS) expand_kernel(
    const float* __restrict__ emb,       // [22, 128]
    float* __restrict__ out,             // [S, 128]
    int S)
{
    __shared__ float s_emb[NUM_CODES * HIDDEN];             // 11 KB
    __shared__ int   s_cnt[ROWS_PER_BLOCK * NUM_CODES];     // 704 ints

    for (int i = threadIdx.x; i < NUM_CODES * HIDDEN; i += ETHREADS)
        s_emb[i] = emb[i];

    const int row0 = blockIdx.x * ROWS_PER_BLOCK;
    const int nrows = min(ROWS_PER_BLOCK, S - row0);
    const int ncnt = nrows * NUM_CODES;

    // stage counts for 32 rows (coalesced int4) and zero-restore in place.
    // 704 ints = 176 int4 per full block; base is int4-aligned (704 % 4 == 0).
    int4* gc4 = reinterpret_cast<int4*>(&g_counts[row0 * NUM_CODES]);
    int4* sc4 = reinterpret_cast<int4*>(s_cnt);
    const int n4 = ncnt >> 2;                                // 176 when full
    for (int i = threadIdx.x; i < n4; i += ETHREADS) {
        sc4[i] = gc4[i];
        gc4[i] = make_int4(0, 0, 0, 0);
    }
    for (int i = (n4 << 2) + threadIdx.x; i < ncnt; i += ETHREADS) {
        s_cnt[i] = g_counts[row0 * NUM_CODES + i];
        g_counts[row0 * NUM_CODES + i] = 0;
    }
    __syncthreads();

    const int lane = threadIdx.x & 31;
    const int warp = threadIdx.x >> 5;                       // 0..7
    const float4* embv = reinterpret_cast<const float4*>(s_emb);
    float4* out4 = reinterpret_cast<float4*>(out);

    #pragma unroll
    for (int rr = 0; rr < ROWS_PER_BLOCK / 8; rr++) {        // 4 rows per warp
        int rl = warp * (ROWS_PER_BLOCK / 8) + rr;
        int row = row0 + rl;
        if (row >= S) break;

        int cnt = (lane < NUM_CODES) ? s_cnt[rl * NUM_CODES + lane] : 0;
        float cntf = (float)cnt;
        unsigned mask = __ballot_sync(0xffffffffu, cnt != 0);

        float4 acc = make_float4(0.f, 0.f, 0.f, 0.f);
        while (mask) {
            int k = __ffs(mask) - 1;
            mask &= mask - 1;
            float f = __shfl_sync(0xffffffffu, cntf, k);
            float4 e = embv[k * 32 + lane];
            acc.x += f * e.x; acc.y += f * e.y;
            acc.z += f * e.z; acc.w += f * e.w;
        }
        out4[(size_t)row * 32 + lane] = acc;
    }
}

extern "C" void kernel_launch(void* const* d_in, const int* in_sizes, int n_in,
                              void* d_out, int out_size)
{
    const int*   x   = (const int*)d_in[0];
    const int*   a2c = (const int*)d_in[1];
    const float* emb = (const float*)d_in[2];
    float*       out = (float*)d_out;

    const int E = in_sizes[1] / 2;                   // 600000
    const int S = out_size / HIDDEN;                 // 100000
    const int* atom_idx  = a2c;
    const int* cycle_idx = a2c + E;

    // 1) histogram edges into (cycle, code) counts, 4 edges/thread
    if ((E & 3) == 0) {
        int E4 = E >> 2;
        count_kernel<<<(E4 + 255) / 256, 256>>>(x, atom_idx, cycle_idx, E4);
    } else {
        count_tail_kernel<<<(E + 255) / 256, 256>>>(x, atom_idx, cycle_idx, E);
    }

    // 2) expand counts -> output rows (32 rows/block); also re-zeros counts
    expand_kernel<<<(S + ROWS_PER_BLOCK - 1) / ROWS_PER_BLOCK, ETHREADS>>>(emb, out, S);
}